// round 9
// baseline (speedup 1.0000x reference)
#include <cuda_runtime.h>
#include <cuda_bf16.h>
#include <math.h>
#include <stdint.h>

// Problem constants (MultiQueryAttention_56358560858478)
#define BB 2
#define TT 2048
#define DD 2048
#define HH 16
#define HD 128
#define MROWS (BB*TT)   // 4096

// ---------------- scratch (no allocation allowed) ----------------
__device__ float  g_Q [MROWS * DD];       // Q projection (B,T,D)
__device__ float  g_K [MROWS * HD];       // tf32-rounded
__device__ float  g_V [MROWS * HD];       // tf32-rounded
__device__ float  g_AO[MROWS * DD];       // attention output, row-major
__device__ float4 g_Xp [MROWS * DD / 4];  // x packed (A-fragment order, tf32)
__device__ float4 g_AOp[MROWS * DD / 4];  // AO packed
__device__ float4 g_WqP[DD * DD / 4];     // weights packed (B-fragment order, tf32)
__device__ float4 g_WkvP[2 * DD * HD / 4];// Wk|Wv packed back-to-back
__device__ float4 g_WoP[DD * DD / 4];

// ---------------- helpers ----------------
__device__ __forceinline__ float f2tf(float x) {
    uint32_t u;
    asm("cvt.rna.tf32.f32 %0, %1;" : "=r"(u) : "f"(x));
    return __uint_as_float(u);
}

__device__ __forceinline__ uint32_t s2u(const void* p) {
    uint32_t a;
    asm("{ .reg .u64 t; cvta.to.shared.u64 t, %1; cvt.u32.u64 %0, t; }" : "=r"(a) : "l"(p));
    return a;
}

__device__ __forceinline__ void mma_tf32(float* d, const uint32_t* a, const uint32_t* b) {
    asm volatile(
        "mma.sync.aligned.m16n8k8.row.col.f32.tf32.tf32.f32 "
        "{%0,%1,%2,%3}, {%4,%5,%6,%7}, {%8,%9}, {%0,%1,%2,%3};"
        : "+f"(d[0]), "+f"(d[1]), "+f"(d[2]), "+f"(d[3])
        : "r"(a[0]), "r"(a[1]), "r"(a[2]), "r"(a[3]), "r"(b[0]), "r"(b[1]));
}

// ================= operand packing =================
__global__ void pack_A(const float* __restrict__ src, float4* __restrict__ dst, int M, int K) {
    const int o = blockIdx.x * 256 + threadIdx.x;
    const int lane = o & 31;
    const int mt   = (o >> 5) & 7;
    const int ks   = (o >> 8) & 3;
    const int tile = o >> 10;
    const int KT = K >> 5;
    const int kc = tile % KT;
    const int mb = tile / KT;
    const int m = mb*128 + mt*16 + (lane >> 2);
    const int k = kc*32 + ks*8 + (lane & 3);
    const float* s = src + (size_t)m * K + k;
    float4 v;
    v.x = f2tf(s[0]);
    v.y = f2tf(s[(size_t)8 * K]);
    v.z = f2tf(s[4]);
    v.w = f2tf(s[(size_t)8 * K + 4]);
    dst[o] = v;
}

__global__ void pack_B(const float* __restrict__ src, float2* __restrict__ dst, int N, int K) {
    const int o = blockIdx.x * 256 + threadIdx.x;
    const int lane = o & 31;
    const int ng   = (o >> 5) & 15;
    const int ks   = (o >> 9) & 3;
    const int tile = o >> 11;
    const int KT = K >> 5;
    const int kc = tile % KT;
    const int nb = tile / KT;
    const int n = nb*128 + ng*8 + (lane >> 2);
    const int k = kc*32 + ks*8 + (lane & 3);
    const float* s = src + (size_t)k * N + n;
    dst[o] = make_float2(f2tf(s[0]), f2tf(s[(size_t)4 * N]));
}

// ================= mma.sync GEMM body (shared by all projections) =================
#define G_STAGE_F 8192
#define G_SMEM (3 * G_STAGE_F * 4)

template<bool ROUND>
__device__ __forceinline__
void gemm_body(const float4* At, const float4* Bt, const float* bias,
               float* C, int N, int KT, int mb, int ncol0, float* sm)
{
    const int tid = threadIdx.x, lane = tid & 31, wid = tid >> 5;
    const int grp = lane >> 2, t4 = lane & 3;
    const int NC = KT;

    float acc[2][8][4];
    #pragma unroll
    for (int i = 0; i < 2; i++)
        #pragma unroll
        for (int j = 0; j < 8; j++)
            #pragma unroll
            for (int e = 0; e < 4; e++) acc[i][j][e] = 0.f;

    auto fill = [&](int ch) {
        const int s = ch % 3;
        const uint32_t da = s2u(sm + s * G_STAGE_F);
        const float4* a = At + (size_t)ch * 1024;
        const float4* b = Bt + (size_t)ch * 1024;
        #pragma unroll
        for (int i = tid; i < 1024; i += 256)
            asm volatile("cp.async.cg.shared.global [%0], [%1], 16;"
                         :: "r"(da + i*16), "l"(a + i));
        const uint32_t db = da + 4096*4;
        #pragma unroll
        for (int i = tid; i < 1024; i += 256)
            asm volatile("cp.async.cg.shared.global [%0], [%1], 16;"
                         :: "r"(db + i*16), "l"(b + i));
        asm volatile("cp.async.commit_group;" ::: "memory");
    };

    fill(0);
    if (NC > 1) fill(1);

    const int mtb = (wid & 3) * 2;
    const int ngb = (wid >> 2) * 8;

    for (int i = 0; i < NC; i++) {
        if (i + 2 < NC) asm volatile("cp.async.wait_group 1;" ::: "memory");
        else            asm volatile("cp.async.wait_group 0;" ::: "memory");
        __syncthreads();
        if (i + 2 < NC) fill(i + 2);

        const float* sa = sm + (i % 3) * G_STAGE_F;
        const float* sb = sa + 4096;
        #pragma unroll
        for (int ks = 0; ks < 4; ks++) {
            float4 a0 = *(const float4*)&sa[ks*1024 + (mtb + 0)*128 + lane*4];
            float4 a1 = *(const float4*)&sa[ks*1024 + (mtb + 1)*128 + lane*4];
            #pragma unroll
            for (int nt = 0; nt < 8; nt++) {
                float2 b = *(const float2*)&sb[ks*1024 + (ngb + nt)*64 + lane*2];
                mma_tf32(acc[0][nt], (const uint32_t*)&a0, (const uint32_t*)&b);
                mma_tf32(acc[1][nt], (const uint32_t*)&a1, (const uint32_t*)&b);
            }
        }
        __syncthreads();
    }

    #pragma unroll
    for (int mt2 = 0; mt2 < 2; mt2++) {
        const int r = mb*128 + (wid & 3)*32 + mt2*16 + grp;
        #pragma unroll
        for (int nt = 0; nt < 8; nt++) {
            const int c = ncol0 + (wid >> 2)*64 + nt*8 + 2*t4;
            const float bz0 = bias[c], bz1 = bias[c+1];
            float v00 = acc[mt2][nt][0] + bz0, v01 = acc[mt2][nt][1] + bz1;
            float v10 = acc[mt2][nt][2] + bz0, v11 = acc[mt2][nt][3] + bz1;
            if (ROUND) { v00 = f2tf(v00); v01 = f2tf(v01); v10 = f2tf(v10); v11 = f2tf(v11); }
            *(float2*)&C[(size_t)r*N + c]     = make_float2(v00, v01);
            *(float2*)&C[(size_t)(r+8)*N + c] = make_float2(v10, v11);
        }
    }
}

__global__ __launch_bounds__(256)
void gemm_mma(const float4* __restrict__ Ap, const float4* __restrict__ Bp,
              const float* __restrict__ bias, float* __restrict__ C,
              int M, int N, int K)
{
    extern __shared__ float sm[];
    const int KT = K >> 5;
    gemm_body<false>(Ap + (size_t)blockIdx.y * KT * 1024,
                     Bp + (size_t)blockIdx.x * KT * 1024,
                     bias, C, N, KT, blockIdx.y, blockIdx.x * 128, sm);
}

// fused K & V projections: blockIdx.x selects K (0) or V (1); output tf32-rounded
__global__ __launch_bounds__(256)
void gemm_kv(const float4* __restrict__ Ap, const float4* __restrict__ Bkv,
             const float* __restrict__ bk, const float* __restrict__ bv,
             float* __restrict__ Kout, float* __restrict__ Vout, int K)
{
    extern __shared__ float sm[];
    const int KT = K >> 5;
    const int sel = blockIdx.x;
    gemm_body<true>(Ap + (size_t)blockIdx.y * KT * 1024,
                    Bkv + (size_t)sel * KT * 1024,
                    sel ? bv : bk, sel ? Vout : Kout,
                    HD, KT, blockIdx.y, 0, sm);
}

// ---------------- flash attention, fragment-packed K/V staging ----------------
// K/V arrive tf32-pre-rounded. Smem (float2 units):
//   Kf[16 ks][8 nt][32 lane], ks-stride 260 (pad 4)  -> S-phase B frag = 1 LDS.64
//   Vf[8 ks][16 nt][32 lane], ks-stride 516 (pad 4)  -> PV-phase B frag = 1 LDS.64
#define FB_R 128
#define FB_C 64
#define PS_ST 68
#define KF_F2 (16*260)            // 4160 float2
#define VF_F2 (8*516)             // 4128 float2
#define PW_OFF ((KF_F2 + VF_F2)*2)  // float offset of Pw region
#define FLASH_SMEM ((PW_OFF + 8*16*PS_ST) * 4)   // 101120 B

__global__ __launch_bounds__(256)
void flash_tf32(const float* __restrict__ Q, const float* __restrict__ Kg,
                const float* __restrict__ Vg, float* __restrict__ O)
{
    extern __shared__ float sm[];
    float2* Kf = (float2*)sm;
    float2* Vf = Kf + KF_F2;
    float*  Pw;

    const int tid  = threadIdx.x;
    const int lane = tid & 31;
    const int wid  = tid >> 5;
    const int grp  = lane >> 2;
    const int t4   = lane & 3;
    Pw = sm + PW_OFF + wid*16*PS_ST;

    const int qb = gridDim.x - 1 - blockIdx.x;
    const int h  = blockIdx.y;
    const int b  = blockIdx.z;
    const int q0 = qb * FB_R;
    const int qr = q0 + wid*16 + grp;

    const float scale = 0.08838834764831845f;

    // Q fragments (scaled + rounded) in registers
    const float* Qb = Q + (size_t)b*TT*DD + (size_t)h*HD;
    uint32_t qf[16][4];
    #pragma unroll
    for (int ks = 0; ks < 16; ks++) {
        const float* p0 = &Qb[(size_t)qr*DD + ks*8 + t4];
        qf[ks][0] = __float_as_uint(f2tf(p0[0]        * scale));
        qf[ks][1] = __float_as_uint(f2tf(p0[8*DD]     * scale));
        qf[ks][2] = __float_as_uint(f2tf(p0[4]        * scale));
        qf[ks][3] = __float_as_uint(f2tf(p0[8*DD + 4] * scale));
    }

    float of[16][4];
    #pragma unroll
    for (int nt = 0; nt < 16; nt++)
        #pragma unroll
        for (int e = 0; e < 4; e++) of[nt][e] = 0.f;

    float m_lo = -1e30f, m_hi = -1e30f, l_lo = 0.f, l_hi = 0.f;

    const float* Kb = Kg + (size_t)b*TT*HD;
    const float* Vb = Vg + (size_t)b*TT*HD;
    const int nkt = 2*(qb + 1);

    for (int kt = 0; kt < nkt; kt++) {
        const int k0 = kt * FB_C;
        __syncthreads();   // prior tile's Kf/Vf reads complete

        // ---- stage K into fragment order: 1024 tasks ----
        #pragma unroll
        for (int p = 0; p < 4; p++) {
            const int task = tid + p*256;
            const int r  = task & 63;
            const int ks = task >> 6;          // 0..15
            const float* s = &Kb[(size_t)(k0 + r)*HD + ks*8];
            float4 u = *(const float4*)s;
            float4 w = *(const float4*)(s + 4);
            float2* d = &Kf[ks*260 + (r >> 3)*32 + (r & 7)*4];
            *(float4*)&d[0] = make_float4(u.x, w.x, u.y, w.y);
            *(float4*)&d[2] = make_float4(u.z, w.z, u.w, w.w);
        }
        // ---- stage V into fragment order: 512 tasks ----
        #pragma unroll
        for (int p = 0; p < 2; p++) {
            const int task = tid + p*256;
            const int rp = task & 31;          // ks = rp>>2, t4v = rp&3
            const int nt = task >> 5;          // 0..15 (hd chunk)
            const int rlo = (rp >> 2)*8 + (rp & 3);
            const float* s0 = &Vb[(size_t)(k0 + rlo)*HD + nt*8];
            const float* s1 = &Vb[(size_t)(k0 + rlo + 4)*HD + nt*8];
            float4 a0 = *(const float4*)s0, a1 = *(const float4*)(s0 + 4);
            float4 c0 = *(const float4*)s1, c1 = *(const float4*)(s1 + 4);
            float2* d = &Vf[(rp >> 2)*516 + nt*32 + (rp & 3)];
            d[0]  = make_float2(a0.x, c0.x);
            d[4]  = make_float2(a0.y, c0.y);
            d[8]  = make_float2(a0.z, c0.z);
            d[12] = make_float2(a0.w, c0.w);
            d[16] = make_float2(a1.x, c1.x);
            d[20] = make_float2(a1.y, c1.y);
            d[24] = make_float2(a1.z, c1.z);
            d[28] = make_float2(a1.w, c1.w);
        }
        __syncthreads();

        // ---- S = Q @ K^T ----
        float sacc[8][4];
        #pragma unroll
        for (int nt = 0; nt < 8; nt++)
            #pragma unroll
            for (int e = 0; e < 4; e++) sacc[nt][e] = 0.f;

        #pragma unroll
        for (int ks = 0; ks < 16; ks++) {
            #pragma unroll
            for (int nt = 0; nt < 8; nt++) {
                float2 bfr = Kf[ks*260 + nt*32 + lane];
                mma_tf32(sacc[nt], qf[ks], (const uint32_t*)&bfr);
            }
        }

        // ---- causal mask ----
        if (kt >= nkt - 2) {
            #pragma unroll
            for (int nt = 0; nt < 8; nt++) {
                int kc = k0 + nt*8 + 2*t4;
                if (kc     > qr)     sacc[nt][0] = -1e30f;
                if (kc + 1 > qr)     sacc[nt][1] = -1e30f;
                if (kc     > qr + 8) sacc[nt][2] = -1e30f;
                if (kc + 1 > qr + 8) sacc[nt][3] = -1e30f;
            }
        }

        // ---- online softmax ----
        float mx_lo = -1e30f, mx_hi = -1e30f;
        #pragma unroll
        for (int nt = 0; nt < 8; nt++) {
            mx_lo = fmaxf(mx_lo, fmaxf(sacc[nt][0], sacc[nt][1]));
            mx_hi = fmaxf(mx_hi, fmaxf(sacc[nt][2], sacc[nt][3]));
        }
        mx_lo = fmaxf(mx_lo, __shfl_xor_sync(0xffffffffu, mx_lo, 1));
        mx_lo = fmaxf(mx_lo, __shfl_xor_sync(0xffffffffu, mx_lo, 2));
        mx_hi = fmaxf(mx_hi, __shfl_xor_sync(0xffffffffu, mx_hi, 1));
        mx_hi = fmaxf(mx_hi, __shfl_xor_sync(0xffffffffu, mx_hi, 2));

        const float mn_lo = fmaxf(m_lo, mx_lo);
        const float mn_hi = fmaxf(m_hi, mx_hi);
        const float corr_lo = __expf(m_lo - mn_lo);
        const float corr_hi = __expf(m_hi - mn_hi);

        float sum_lo = 0.f, sum_hi = 0.f;
        #pragma unroll
        for (int nt = 0; nt < 8; nt++) {
            sacc[nt][0] = __expf(sacc[nt][0] - mn_lo);
            sacc[nt][1] = __expf(sacc[nt][1] - mn_lo);
            sacc[nt][2] = __expf(sacc[nt][2] - mn_hi);
            sacc[nt][3] = __expf(sacc[nt][3] - mn_hi);
            sum_lo += sacc[nt][0] + sacc[nt][1];
            sum_hi += sacc[nt][2] + sacc[nt][3];
        }
        sum_lo += __shfl_xor_sync(0xffffffffu, sum_lo, 1);
        sum_lo += __shfl_xor_sync(0xffffffffu, sum_lo, 2);
        sum_hi += __shfl_xor_sync(0xffffffffu, sum_hi, 1);
        sum_hi += __shfl_xor_sync(0xffffffffu, sum_hi, 2);

        l_lo = l_lo * corr_lo + sum_lo;  m_lo = mn_lo;
        l_hi = l_hi * corr_hi + sum_hi;  m_hi = mn_hi;

        #pragma unroll
        for (int nt = 0; nt < 16; nt++) {
            of[nt][0] *= corr_lo;  of[nt][1] *= corr_lo;
            of[nt][2] *= corr_hi;  of[nt][3] *= corr_hi;
        }

        // ---- P through per-warp smem (C-layout -> A-layout), tf32 ----
        #pragma unroll
        for (int nt = 0; nt < 8; nt++) {
            float2 p01 = make_float2(f2tf(sacc[nt][0]), f2tf(sacc[nt][1]));
            *(float2*)&Pw[grp*PS_ST + nt*8 + 2*t4] = p01;
            float2 p23 = make_float2(f2tf(sacc[nt][2]), f2tf(sacc[nt][3]));
            *(float2*)&Pw[(grp + 8)*PS_ST + nt*8 + 2*t4] = p23;
        }
        __syncwarp();

        // ---- O += P @ V ----
        #pragma unroll
        for (int ks = 0; ks < 8; ks++) {
            uint32_t pf[4];
            const float* pb = &Pw[grp*PS_ST + ks*8 + t4];
            pf[0] = __float_as_uint(pb[0]);
            pf[1] = __float_as_uint(pb[8*PS_ST]);
            pf[2] = __float_as_uint(pb[4]);
            pf[3] = __float_as_uint(pb[8*PS_ST + 4]);
            #pragma unroll
            for (int nt = 0; nt < 16; nt++) {
                float2 bfr = Vf[ks*516 + nt*32 + lane];
                mma_tf32(of[nt], pf, (const uint32_t*)&bfr);
            }
        }
    }

    // normalize, round to tf32 (feeds packed O-proj GEMM), write
    const float inv_lo = 1.f / l_lo;
    const float inv_hi = 1.f / l_hi;
    float* Ob = O + (size_t)b*TT*DD + (size_t)h*HD;
    #pragma unroll
    for (int nt = 0; nt < 16; nt++) {
        const int c = nt*8 + 2*t4;
        float2 v0 = make_float2(f2tf(of[nt][0]*inv_lo), f2tf(of[nt][1]*inv_lo));
        *(float2*)&Ob[(size_t)qr*DD + c] = v0;
        float2 v1 = make_float2(f2tf(of[nt][2]*inv_hi), f2tf(of[nt][3]*inv_hi));
        *(float2*)&Ob[(size_t)(qr + 8)*DD + c] = v1;
    }
}

// ---------------- launch ----------------
extern "C" void kernel_launch(void* const* d_in, const int* in_sizes, int n_in,
                              void* d_out, int out_size)
{
    const float* x  = (const float*)d_in[0];
    const float* Wq = (const float*)d_in[1];
    const float* bq = (const float*)d_in[2];
    const float* Wk = (const float*)d_in[3];
    const float* bk = (const float*)d_in[4];
    const float* Wv = (const float*)d_in[5];
    const float* bv = (const float*)d_in[6];
    const float* Wo = (const float*)d_in[7];
    const float* bo = (const float*)d_in[8];
    float* out = (float*)d_out;

    float *Qp, *Kp, *Vp, *AOr;
    float4 *Xp, *AOp, *WqP, *WkvP, *WoP;
    cudaGetSymbolAddress((void**)&Qp,   g_Q);
    cudaGetSymbolAddress((void**)&Kp,   g_K);
    cudaGetSymbolAddress((void**)&Vp,   g_V);
    cudaGetSymbolAddress((void**)&AOr,  g_AO);
    cudaGetSymbolAddress((void**)&Xp,   g_Xp);
    cudaGetSymbolAddress((void**)&AOp,  g_AOp);
    cudaGetSymbolAddress((void**)&WqP,  g_WqP);
    cudaGetSymbolAddress((void**)&WkvP, g_WkvP);
    cudaGetSymbolAddress((void**)&WoP,  g_WoP);

    cudaFuncSetAttribute(gemm_mma,  cudaFuncAttributeMaxDynamicSharedMemorySize, G_SMEM);
    cudaFuncSetAttribute(gemm_kv,   cudaFuncAttributeMaxDynamicSharedMemorySize, G_SMEM);
    cudaFuncSetAttribute(flash_tf32, cudaFuncAttributeMaxDynamicSharedMemorySize, FLASH_SMEM);

    // ---- pack operands (tf32-rounded, fragment order) ----
    pack_A<<<MROWS*DD/4/256, 256>>>(x,  Xp,  MROWS, DD);
    pack_B<<<DD*DD/2/256,    256>>>(Wq, (float2*)WqP, DD, DD);
    pack_B<<<DD*HD/2/256,    256>>>(Wk, (float2*)WkvP, HD, DD);
    pack_B<<<DD*HD/2/256,    256>>>(Wv, (float2*)WkvP + DD*HD/2, HD, DD);
    pack_B<<<DD*DD/2/256,    256>>>(Wo, (float2*)WoP, DD, DD);

    // ---- projections ----
    gemm_mma<<<dim3(DD/128, MROWS/128), 256, G_SMEM>>>(Xp, WqP, bq, Qp, MROWS, DD, DD);
    gemm_kv <<<dim3(2,      MROWS/128), 256, G_SMEM>>>(Xp, WkvP, bk, bv, Kp, Vp, DD);

    // ---- attention ----
    flash_tf32<<<dim3(TT/FB_R, HH, BB), 256, FLASH_SMEM>>>(Qp, Kp, Vp, AOr);

    // ---- output projection ----
    pack_A<<<MROWS*DD/4/256, 256>>>(AOr, AOp, MROWS, DD);
    gemm_mma<<<dim3(DD/128, MROWS/128), 256, G_SMEM>>>(AOp, WoP, bo, out, MROWS, DD, DD);
}

// round 11
// speedup vs baseline: 1.2529x; 1.2529x over previous
#include <cuda_runtime.h>
#include <cuda_bf16.h>
#include <math.h>
#include <stdint.h>

// Problem constants (MultiQueryAttention_56358560858478)
#define BB 2
#define TT 2048
#define DD 2048
#define HH 16
#define HD 128
#define MROWS (BB*TT)   // 4096
#define KV_TILES (MROWS/64)   // 64 tiles of 64 keys (both batches)

// ---------------- scratch (no allocation allowed) ----------------
__device__ float  g_Q [MROWS * DD];       // Q projection (B,T,D)
__device__ float  g_K [MROWS * HD];       // tf32-rounded, row-major
__device__ float  g_V [MROWS * HD];       // tf32-rounded, row-major
__device__ float2 g_Kf[KV_TILES * 4096];  // K fragment-packed per 64-key tile
__device__ float2 g_Vf[KV_TILES * 4096];  // V fragment-packed per 64-key tile
__device__ float  g_AO[MROWS * DD];       // attention output, row-major
__device__ float4 g_Xp [MROWS * DD / 4];  // x packed (A-fragment order, tf32)
__device__ float4 g_AOp[MROWS * DD / 4];  // AO packed
__device__ float4 g_WqP[DD * DD / 4];     // weights packed (B-fragment order, tf32)
__device__ float4 g_WkvP[2 * DD * HD / 4];// Wk|Wv packed back-to-back
__device__ float4 g_WoP[DD * DD / 4];

// ---------------- helpers ----------------
__device__ __forceinline__ float f2tf(float x) {
    uint32_t u;
    asm("cvt.rna.tf32.f32 %0, %1;" : "=r"(u) : "f"(x));
    return __uint_as_float(u);
}

__device__ __forceinline__ uint32_t s2u(const void* p) {
    uint32_t a;
    asm("{ .reg .u64 t; cvta.to.shared.u64 t, %1; cvt.u32.u64 %0, t; }" : "=r"(a) : "l"(p));
    return a;
}

__device__ __forceinline__ void mma_tf32(float* d, const uint32_t* a, const uint32_t* b) {
    asm volatile(
        "mma.sync.aligned.m16n8k8.row.col.f32.tf32.tf32.f32 "
        "{%0,%1,%2,%3}, {%4,%5,%6,%7}, {%8,%9}, {%0,%1,%2,%3};"
        : "+f"(d[0]), "+f"(d[1]), "+f"(d[2]), "+f"(d[3])
        : "r"(a[0]), "r"(a[1]), "r"(a[2]), "r"(a[3]), "r"(b[0]), "r"(b[1]));
}

// ================= operand packing (GEMM; unchanged from R5) =================
__global__ void pack_A(const float* __restrict__ src, float4* __restrict__ dst, int M, int K) {
    const int o = blockIdx.x * 256 + threadIdx.x;
    const int lane = o & 31;
    const int mt   = (o >> 5) & 7;
    const int ks   = (o >> 8) & 3;
    const int tile = o >> 10;
    const int KT = K >> 5;
    const int kc = tile % KT;
    const int mb = tile / KT;
    const int m = mb*128 + mt*16 + (lane >> 2);
    const int k = kc*32 + ks*8 + (lane & 3);
    const float* s = src + (size_t)m * K + k;
    float4 v;
    v.x = f2tf(s[0]);
    v.y = f2tf(s[(size_t)8 * K]);
    v.z = f2tf(s[4]);
    v.w = f2tf(s[(size_t)8 * K + 4]);
    dst[o] = v;
}

__global__ void pack_B(const float* __restrict__ src, float2* __restrict__ dst, int N, int K) {
    const int o = blockIdx.x * 256 + threadIdx.x;
    const int lane = o & 31;
    const int ng   = (o >> 5) & 15;
    const int ks   = (o >> 9) & 3;
    const int tile = o >> 11;
    const int KT = K >> 5;
    const int kc = tile % KT;
    const int nb = tile / KT;
    const int n = nb*128 + ng*8 + (lane >> 2);
    const int k = kc*32 + ks*8 + (lane & 3);
    const float* s = src + (size_t)k * N + n;
    dst[o] = make_float2(f2tf(s[0]), f2tf(s[(size_t)4 * N]));
}

// ================= K/V fragment packing (one-off, values already tf32) =================
// K tile fragment: Kf[tile][ks(16)][nt(8)][lane]  = {K[t*64+nt*8+grp][ks*8+t4], ...+4}
// V tile fragment: Vf[tile][ks(8)][nt(16)][lane]  = {V[t*64+ks*8+t4][nt*8+grp], V[+4 row][...]}
__global__ void pack_kv(const float* __restrict__ Kg, const float* __restrict__ Vg,
                        float2* __restrict__ Kfp, float2* __restrict__ Vfp)
{
    const int o = blockIdx.x * 256 + threadIdx.x;      // 0 .. 2*KV_TILES*4096-1
    const int sel = o >> 18;                           // KV_TILES*4096 = 262144
    const int oo = o & 262143;
    const int lane = oo & 31;
    const int tile = oo >> 12;
    if (sel == 0) {
        const int nt = (oo >> 5) & 7;
        const int ks = (oo >> 8) & 15;
        const int row = tile*64 + nt*8 + (lane >> 2);
        const int k = ks*8 + (lane & 3);
        const float* s = Kg + (size_t)row*HD + k;
        Kfp[oo] = make_float2(s[0], s[4]);
    } else {
        const int nt = (oo >> 5) & 15;
        const int ks = (oo >> 9) & 7;
        const int row = tile*64 + ks*8 + (lane & 3);
        const int n = nt*8 + (lane >> 2);
        const float* s = Vg + (size_t)row*HD + n;
        Vfp[oo] = make_float2(s[0], s[(size_t)4*HD]);
    }
}

// ================= mma.sync GEMM body (unchanged from R5) =================
#define G_STAGE_F 8192
#define G_SMEM (3 * G_STAGE_F * 4)

template<bool ROUND>
__device__ __forceinline__
void gemm_body(const float4* At, const float4* Bt, const float* bias,
               float* C, int N, int KT, int mb, int ncol0, float* sm)
{
    const int tid = threadIdx.x, lane = tid & 31, wid = tid >> 5;
    const int grp = lane >> 2, t4 = lane & 3;
    const int NC = KT;

    float acc[2][8][4];
    #pragma unroll
    for (int i = 0; i < 2; i++)
        #pragma unroll
        for (int j = 0; j < 8; j++)
            #pragma unroll
            for (int e = 0; e < 4; e++) acc[i][j][e] = 0.f;

    auto fill = [&](int ch) {
        const int s = ch % 3;
        const uint32_t da = s2u(sm + s * G_STAGE_F);
        const float4* a = At + (size_t)ch * 1024;
        const float4* b = Bt + (size_t)ch * 1024;
        #pragma unroll
        for (int i = tid; i < 1024; i += 256)
            asm volatile("cp.async.cg.shared.global [%0], [%1], 16;"
                         :: "r"(da + i*16), "l"(a + i));
        const uint32_t db = da + 4096*4;
        #pragma unroll
        for (int i = tid; i < 1024; i += 256)
            asm volatile("cp.async.cg.shared.global [%0], [%1], 16;"
                         :: "r"(db + i*16), "l"(b + i));
        asm volatile("cp.async.commit_group;" ::: "memory");
    };

    fill(0);
    if (NC > 1) fill(1);

    const int mtb = (wid & 3) * 2;
    const int ngb = (wid >> 2) * 8;

    for (int i = 0; i < NC; i++) {
        if (i + 2 < NC) asm volatile("cp.async.wait_group 1;" ::: "memory");
        else            asm volatile("cp.async.wait_group 0;" ::: "memory");
        __syncthreads();
        if (i + 2 < NC) fill(i + 2);

        const float* sa = sm + (i % 3) * G_STAGE_F;
        const float* sb = sa + 4096;
        #pragma unroll
        for (int ks = 0; ks < 4; ks++) {
            float4 a0 = *(const float4*)&sa[ks*1024 + (mtb + 0)*128 + lane*4];
            float4 a1 = *(const float4*)&sa[ks*1024 + (mtb + 1)*128 + lane*4];
            #pragma unroll
            for (int nt = 0; nt < 8; nt++) {
                float2 b = *(const float2*)&sb[ks*1024 + (ngb + nt)*64 + lane*2];
                mma_tf32(acc[0][nt], (const uint32_t*)&a0, (const uint32_t*)&b);
                mma_tf32(acc[1][nt], (const uint32_t*)&a1, (const uint32_t*)&b);
            }
        }
        __syncthreads();
    }

    #pragma unroll
    for (int mt2 = 0; mt2 < 2; mt2++) {
        const int r = mb*128 + (wid & 3)*32 + mt2*16 + grp;
        #pragma unroll
        for (int nt = 0; nt < 8; nt++) {
            const int c = ncol0 + (wid >> 2)*64 + nt*8 + 2*t4;
            const float bz0 = bias[c], bz1 = bias[c+1];
            float v00 = acc[mt2][nt][0] + bz0, v01 = acc[mt2][nt][1] + bz1;
            float v10 = acc[mt2][nt][2] + bz0, v11 = acc[mt2][nt][3] + bz1;
            if (ROUND) { v00 = f2tf(v00); v01 = f2tf(v01); v10 = f2tf(v10); v11 = f2tf(v11); }
            *(float2*)&C[(size_t)r*N + c]     = make_float2(v00, v01);
            *(float2*)&C[(size_t)(r+8)*N + c] = make_float2(v10, v11);
        }
    }
}

__global__ __launch_bounds__(256)
void gemm_mma(const float4* __restrict__ Ap, const float4* __restrict__ Bp,
              const float* __restrict__ bias, float* __restrict__ C,
              int M, int N, int K)
{
    extern __shared__ float sm[];
    const int KT = K >> 5;
    gemm_body<false>(Ap + (size_t)blockIdx.y * KT * 1024,
                     Bp + (size_t)blockIdx.x * KT * 1024,
                     bias, C, N, KT, blockIdx.y, blockIdx.x * 128, sm);
}

__global__ __launch_bounds__(256)
void gemm_kv(const float4* __restrict__ Ap, const float4* __restrict__ Bkv,
             const float* __restrict__ bk, const float* __restrict__ bv,
             float* __restrict__ Kout, float* __restrict__ Vout, int K)
{
    extern __shared__ float sm[];
    const int KT = K >> 5;
    const int sel = blockIdx.x;
    gemm_body<true>(Ap + (size_t)blockIdx.y * KT * 1024,
                    Bkv + (size_t)sel * KT * 1024,
                    sel ? bv : bk, sel ? Vout : Kout,
                    HD, KT, blockIdx.y, 0, sm);
}

// ---------------- flash attention: pre-packed K/V tiles, cp.async double-buffer ----
// Stage = [Kf 4096 float2][Vf 4096 float2] = 64KB. 2 stages + Pw.
#define FB_R 128
#define PS_ST 68
#define F_STAGE_F2 8192
#define PW_OFF (2*F_STAGE_F2*2)                     // float offset of Pw region
#define FLASH_SMEM ((PW_OFF + 8*16*PS_ST) * 4)      // 165888 B

__global__ __launch_bounds__(256)
void flash_tf32(const float* __restrict__ Q,
                const float2* __restrict__ Kfp, const float2* __restrict__ Vfp,
                float* __restrict__ O)
{
    extern __shared__ float sm[];
    const uint32_t sb = s2u(sm);

    const int tid  = threadIdx.x;
    const int lane = tid & 31;
    const int wid  = tid >> 5;
    const int grp  = lane >> 2;
    const int t4   = lane & 3;
    float* Pw = sm + PW_OFF + wid*16*PS_ST;

    const int qb = gridDim.x - 1 - blockIdx.x;   // longest blocks first
    const int h  = blockIdx.y;
    const int b  = blockIdx.z;
    const int q0 = qb * FB_R;
    const int qr = q0 + wid*16 + grp;

    const float scale = 0.08838834764831845f;

    // Q fragments (scaled + rounded) in registers
    const float* Qb = Q + (size_t)b*TT*DD + (size_t)h*HD;
    uint32_t qf[16][4];
    #pragma unroll
    for (int ks = 0; ks < 16; ks++) {
        const float* p0 = &Qb[(size_t)qr*DD + ks*8 + t4];
        qf[ks][0] = __float_as_uint(f2tf(p0[0]        * scale));
        qf[ks][1] = __float_as_uint(f2tf(p0[8*DD]     * scale));
        qf[ks][2] = __float_as_uint(f2tf(p0[4]        * scale));
        qf[ks][3] = __float_as_uint(f2tf(p0[8*DD + 4] * scale));
    }

    float of[16][4];
    #pragma unroll
    for (int nt = 0; nt < 16; nt++)
        #pragma unroll
        for (int e = 0; e < 4; e++) of[nt][e] = 0.f;

    float m_lo = -1e30f, m_hi = -1e30f, l_lo = 0.f, l_hi = 0.f;

    const float4* Kt = (const float4*)(Kfp + (size_t)b*(TT/64)*4096);  // per-batch tiles
    const float4* Vt = (const float4*)(Vfp + (size_t)b*(TT/64)*4096);
    const int nkt = 2*(qb + 1);

    auto fill = [&](int t) {
        const uint32_t dst = sb + (uint32_t)(t & 1) * 65536;
        const float4* sk = Kt + (size_t)t * 2048;
        const float4* sv = Vt + (size_t)t * 2048;
        #pragma unroll
        for (int i = 0; i < 8; i++) {
            const int idx = tid + i*256;
            asm volatile("cp.async.cg.shared.global [%0], [%1], 16;"
                         :: "r"(dst + idx*16), "l"(sk + idx));
            asm volatile("cp.async.cg.shared.global [%0], [%1], 16;"
                         :: "r"(dst + 32768 + idx*16), "l"(sv + idx));
        }
        asm volatile("cp.async.commit_group;" ::: "memory");
    };

    fill(0);
    for (int kt = 0; kt < nkt; kt++) {
        if (kt + 1 < nkt) { fill(kt + 1); asm volatile("cp.async.wait_group 1;" ::: "memory"); }
        else              { asm volatile("cp.async.wait_group 0;" ::: "memory"); }
        __syncthreads();

        const float2* Kf = (const float2*)sm + (size_t)(kt & 1) * F_STAGE_F2;
        const float2* Vf = Kf + 4096;
        const int k0 = kt * 64;

        // ---- S = Q @ K^T ----
        float sacc[8][4];
        #pragma unroll
        for (int nt = 0; nt < 8; nt++)
            #pragma unroll
            for (int e = 0; e < 4; e++) sacc[nt][e] = 0.f;

        #pragma unroll
        for (int ks = 0; ks < 16; ks++) {
            #pragma unroll
            for (int nt = 0; nt < 8; nt++) {
                float2 bfr = Kf[ks*256 + nt*32 + lane];
                mma_tf32(sacc[nt], qf[ks], (const uint32_t*)&bfr);
            }
        }

        // ---- causal mask (only last two tiles overlap the diagonal) ----
        if (kt >= nkt - 2) {
            #pragma unroll
            for (int nt = 0; nt < 8; nt++) {
                int kc = k0 + nt*8 + 2*t4;
                if (kc     > qr)     sacc[nt][0] = -1e30f;
                if (kc + 1 > qr)     sacc[nt][1] = -1e30f;
                if (kc     > qr + 8) sacc[nt][2] = -1e30f;
                if (kc + 1 > qr + 8) sacc[nt][3] = -1e30f;
            }
        }

        // ---- online softmax ----
        float mx_lo = -1e30f, mx_hi = -1e30f;
        #pragma unroll
        for (int nt = 0; nt < 8; nt++) {
            mx_lo = fmaxf(mx_lo, fmaxf(sacc[nt][0], sacc[nt][1]));
            mx_hi = fmaxf(mx_hi, fmaxf(sacc[nt][2], sacc[nt][3]));
        }
        mx_lo = fmaxf(mx_lo, __shfl_xor_sync(0xffffffffu, mx_lo, 1));
        mx_lo = fmaxf(mx_lo, __shfl_xor_sync(0xffffffffu, mx_lo, 2));
        mx_hi = fmaxf(mx_hi, __shfl_xor_sync(0xffffffffu, mx_hi, 1));
        mx_hi = fmaxf(mx_hi, __shfl_xor_sync(0xffffffffu, mx_hi, 2));

        const float mn_lo = fmaxf(m_lo, mx_lo);
        const float mn_hi = fmaxf(m_hi, mx_hi);
        const float corr_lo = __expf(m_lo - mn_lo);
        const float corr_hi = __expf(m_hi - mn_hi);

        float sum_lo = 0.f, sum_hi = 0.f;
        #pragma unroll
        for (int nt = 0; nt < 8; nt++) {
            sacc[nt][0] = __expf(sacc[nt][0] - mn_lo);
            sacc[nt][1] = __expf(sacc[nt][1] - mn_lo);
            sacc[nt][2] = __expf(sacc[nt][2] - mn_hi);
            sacc[nt][3] = __expf(sacc[nt][3] - mn_hi);
            sum_lo += sacc[nt][0] + sacc[nt][1];
            sum_hi += sacc[nt][2] + sacc[nt][3];
        }
        sum_lo += __shfl_xor_sync(0xffffffffu, sum_lo, 1);
        sum_lo += __shfl_xor_sync(0xffffffffu, sum_lo, 2);
        sum_hi += __shfl_xor_sync(0xffffffffu, sum_hi, 1);
        sum_hi += __shfl_xor_sync(0xffffffffu, sum_hi, 2);

        l_lo = l_lo * corr_lo + sum_lo;  m_lo = mn_lo;
        l_hi = l_hi * corr_hi + sum_hi;  m_hi = mn_hi;

        #pragma unroll
        for (int nt = 0; nt < 16; nt++) {
            of[nt][0] *= corr_lo;  of[nt][1] *= corr_lo;
            of[nt][2] *= corr_hi;  of[nt][3] *= corr_hi;
        }

        // ---- P through per-warp smem (C-layout -> A-layout), tf32 ----
        #pragma unroll
        for (int nt = 0; nt < 8; nt++) {
            float2 p01 = make_float2(f2tf(sacc[nt][0]), f2tf(sacc[nt][1]));
            *(float2*)&Pw[grp*PS_ST + nt*8 + 2*t4] = p01;
            float2 p23 = make_float2(f2tf(sacc[nt][2]), f2tf(sacc[nt][3]));
            *(float2*)&Pw[(grp + 8)*PS_ST + nt*8 + 2*t4] = p23;
        }
        __syncwarp();

        // ---- O += P @ V ----
        #pragma unroll
        for (int ks = 0; ks < 8; ks++) {
            uint32_t pf[4];
            const float* pb = &Pw[grp*PS_ST + ks*8 + t4];
            pf[0] = __float_as_uint(pb[0]);
            pf[1] = __float_as_uint(pb[8*PS_ST]);
            pf[2] = __float_as_uint(pb[4]);
            pf[3] = __float_as_uint(pb[8*PS_ST + 4]);
            #pragma unroll
            for (int nt = 0; nt < 16; nt++) {
                float2 bfr = Vf[ks*512 + nt*32 + lane];
                mma_tf32(of[nt], pf, (const uint32_t*)&bfr);
            }
        }
        __syncthreads();   // stage reads done before next fill overwrites
    }

    // normalize, round to tf32 (feeds packed O-proj GEMM), write
    const float inv_lo = 1.f / l_lo;
    const float inv_hi = 1.f / l_hi;
    float* Ob = O + (size_t)b*TT*DD + (size_t)h*HD;
    #pragma unroll
    for (int nt = 0; nt < 16; nt++) {
        const int c = nt*8 + 2*t4;
        float2 v0 = make_float2(f2tf(of[nt][0]*inv_lo), f2tf(of[nt][1]*inv_lo));
        *(float2*)&Ob[(size_t)qr*DD + c] = v0;
        float2 v1 = make_float2(f2tf(of[nt][2]*inv_hi), f2tf(of[nt][3]*inv_hi));
        *(float2*)&Ob[(size_t)(qr + 8)*DD + c] = v1;
    }
}

// ---------------- launch ----------------
extern "C" void kernel_launch(void* const* d_in, const int* in_sizes, int n_in,
                              void* d_out, int out_size)
{
    const float* x  = (const float*)d_in[0];
    const float* Wq = (const float*)d_in[1];
    const float* bq = (const float*)d_in[2];
    const float* Wk = (const float*)d_in[3];
    const float* bk = (const float*)d_in[4];
    const float* Wv = (const float*)d_in[5];
    const float* bv = (const float*)d_in[6];
    const float* Wo = (const float*)d_in[7];
    const float* bo = (const float*)d_in[8];
    float* out = (float*)d_out;

    float *Qp, *Kp, *Vp, *AOr;
    float2 *Kfp, *Vfp;
    float4 *Xp, *AOp, *WqP, *WkvP, *WoP;
    cudaGetSymbolAddress((void**)&Qp,   g_Q);
    cudaGetSymbolAddress((void**)&Kp,   g_K);
    cudaGetSymbolAddress((void**)&Vp,   g_V);
    cudaGetSymbolAddress((void**)&Kfp,  g_Kf);
    cudaGetSymbolAddress((void**)&Vfp,  g_Vf);
    cudaGetSymbolAddress((void**)&AOr,  g_AO);
    cudaGetSymbolAddress((void**)&Xp,   g_Xp);
    cudaGetSymbolAddress((void**)&AOp,  g_AOp);
    cudaGetSymbolAddress((void**)&WqP,  g_WqP);
    cudaGetSymbolAddress((void**)&WkvP, g_WkvP);
    cudaGetSymbolAddress((void**)&WoP,  g_WoP);

    cudaFuncSetAttribute(gemm_mma,  cudaFuncAttributeMaxDynamicSharedMemorySize, G_SMEM);
    cudaFuncSetAttribute(gemm_kv,   cudaFuncAttributeMaxDynamicSharedMemorySize, G_SMEM);
    cudaFuncSetAttribute(flash_tf32, cudaFuncAttributeMaxDynamicSharedMemorySize, FLASH_SMEM);

    // ---- pack GEMM operands (tf32-rounded, fragment order) ----
    pack_A<<<MROWS*DD/4/256, 256>>>(x,  Xp,  MROWS, DD);
    pack_B<<<DD*DD/2/256,    256>>>(Wq, (float2*)WqP, DD, DD);
    pack_B<<<DD*HD/2/256,    256>>>(Wk, (float2*)WkvP, HD, DD);
    pack_B<<<DD*HD/2/256,    256>>>(Wv, (float2*)WkvP + DD*HD/2, HD, DD);
    pack_B<<<DD*DD/2/256,    256>>>(Wo, (float2*)WoP, DD, DD);

    // ---- projections ----
    gemm_mma<<<dim3(DD/128, MROWS/128), 256, G_SMEM>>>(Xp, WqP, bq, Qp, MROWS, DD, DD);
    gemm_kv <<<dim3(2,      MROWS/128), 256, G_SMEM>>>(Xp, WkvP, bk, bv, Kp, Vp, DD);

    // ---- pack K/V into fragment-ordered tiles ----
    pack_kv<<<2*KV_TILES*4096/256, 256>>>(Kp, Vp, Kfp, Vfp);

    // ---- attention ----
    flash_tf32<<<dim3(TT/FB_R, HH, BB), 256, FLASH_SMEM>>>(Qp, Kfp, Vfp, AOr);

    // ---- output projection ----
    pack_A<<<MROWS*DD/4/256, 256>>>(AOr, AOp, MROWS, DD);
    gemm_mma<<<dim3(DD/128, MROWS/128), 256, G_SMEM>>>(AOp, WoP, bo, out, MROWS, DD, DD);
}